// round 1
// baseline (speedup 1.0000x reference)
#include <cuda_runtime.h>
#include <math.h>

#define BB   2
#define SS   2048
#define HID  1024
#define HH   16
#define DD   64
#define ROTD 32
#define MTOT (BB*SS)   // 4096

// Scratch (allocation-free rule: static __device__ arrays)
__device__ float g_q[MTOT*HID];
__device__ float g_k[MTOT*HID];
__device__ float g_v[MTOT*HID];
__device__ float g_attn[MTOT*HID];
__device__ float g_scores[(size_t)BB*HH*SS*SS];   // 512 MB

// ---------------------------------------------------------------------------
// Generic row-major SGEMM: C[M,N] = A[M,K] @ B[K,N] (+bias). 64x64 tile,
// 4x4 microtile, 256 threads, BK=16. All dims multiples of 64/16.
// ---------------------------------------------------------------------------
__global__ __launch_bounds__(256) void sgemm_nn(
    const float* __restrict__ A, const float* __restrict__ Bm,
    const float* __restrict__ bias, float* __restrict__ C,
    int M, int N, int K)
{
    __shared__ float As[16][68];   // [k][m]
    __shared__ float Bs[16][68];   // [k][n]
    const int tid = threadIdx.x;
    const int tx = tid & 15, ty = tid >> 4;
    const int bm = blockIdx.y << 6, bn = blockIdx.x << 6;
    const int arow = tid >> 2, ak = (tid & 3) << 2;
    const int bk = tid >> 4, bn4 = (tid & 15) << 2;
    float acc[4][4] = {};

    const float* Aptr = A + (size_t)(bm + arow) * K + ak;
    const float* Bptr = Bm + (size_t)bk * N + bn + bn4;

    for (int k0 = 0; k0 < K; k0 += 16) {
        float4 av = *(const float4*)(Aptr + k0);
        float4 bv = *(const float4*)(Bptr + (size_t)k0 * N);
        As[ak+0][arow] = av.x; As[ak+1][arow] = av.y;
        As[ak+2][arow] = av.z; As[ak+3][arow] = av.w;
        *(float4*)&Bs[bk][bn4] = bv;
        __syncthreads();
        #pragma unroll
        for (int kk = 0; kk < 16; kk++) {
            float4 a = *(const float4*)&As[kk][ty << 2];
            float4 b = *(const float4*)&Bs[kk][tx << 2];
            float a4[4] = {a.x, a.y, a.z, a.w};
            float b4[4] = {b.x, b.y, b.z, b.w};
            #pragma unroll
            for (int i = 0; i < 4; i++)
                #pragma unroll
                for (int j = 0; j < 4; j++)
                    acc[i][j] += a4[i] * b4[j];
        }
        __syncthreads();
    }

    float4 bb = make_float4(0.f, 0.f, 0.f, 0.f);
    if (bias) bb = *(const float4*)&bias[bn + (tx << 2)];
    #pragma unroll
    for (int i = 0; i < 4; i++) {
        float4 c;
        c.x = acc[i][0] + bb.x; c.y = acc[i][1] + bb.y;
        c.z = acc[i][2] + bb.z; c.w = acc[i][3] + bb.w;
        *(float4*)&C[(size_t)(bm + (ty << 2) + i) * N + bn + (tx << 2)] = c;
    }
}

// ---------------------------------------------------------------------------
// Rotary (reference reduces to an elementwise factor) + q scale by 1/sqrt(D).
// q/k layout: (B,S,H,D) flattened to (B*S, HID). sinusoids: (B,2,S,ROT).
// ---------------------------------------------------------------------------
__global__ __launch_bounds__(256) void rotary_scale(
    float* __restrict__ q, float* __restrict__ k,
    const float* __restrict__ sinu)
{
    int idx = blockIdx.x * 256 + threadIdx.x;   // < MTOT*HID
    int d   = idx & 63;
    int row = idx >> 10;          // b*S + s
    int b   = row >> 11;
    int s   = row & (SS - 1);
    float f = 1.0f;
    if (d < ROTD) {
        float sn = sinu[(((size_t)b * 2 + 0) * SS + s) * ROTD + d];
        float cs = sinu[(((size_t)b * 2 + 1) * SS + s) * ROTD + d];
        f = cs + ((d & 1) ? sn : -sn);
    }
    q[idx] *= f * 0.125f;   // 1/sqrt(64)
    k[idx] *= f;
}

// ---------------------------------------------------------------------------
// scores[z=b*H+h][i][j] = sum_d q[b,i,h,d]*k[b,j,h,d]   (K = D = 64, one pass)
// ---------------------------------------------------------------------------
__global__ __launch_bounds__(256) void attn_scores(
    const float* __restrict__ q, const float* __restrict__ k,
    float* __restrict__ scores)
{
    __shared__ float Qs[64][68];   // [d][i]
    __shared__ float Ks[64][68];   // [d][j]
    const int tid = threadIdx.x;
    const int tx = tid & 15, ty = tid >> 4;
    const int z = blockIdx.z;
    const int b = z >> 4, h = z & 15;
    const float* qp = q + (size_t)b * SS * HID + h * DD;
    const float* kp = k + (size_t)b * SS * HID + h * DD;
    float* sp = scores + (size_t)z * SS * SS;
    const int bi = blockIdx.y << 6, bj = blockIdx.x << 6;
    const int lr = tid >> 4;
    const int d4 = (tid & 15) << 2;

    #pragma unroll
    for (int it = 0; it < 4; it++) {
        int r = lr + (it << 4);
        float4 qv = *(const float4*)&qp[(size_t)(bi + r) * HID + d4];
        float4 kv = *(const float4*)&kp[(size_t)(bj + r) * HID + d4];
        Qs[d4+0][r] = qv.x; Qs[d4+1][r] = qv.y; Qs[d4+2][r] = qv.z; Qs[d4+3][r] = qv.w;
        Ks[d4+0][r] = kv.x; Ks[d4+1][r] = kv.y; Ks[d4+2][r] = kv.z; Ks[d4+3][r] = kv.w;
    }
    __syncthreads();

    float acc[4][4] = {};
    #pragma unroll 16
    for (int d = 0; d < 64; d++) {
        float4 a = *(const float4*)&Qs[d][ty << 2];
        float4 b4v = *(const float4*)&Ks[d][tx << 2];
        float a4[4] = {a.x, a.y, a.z, a.w};
        float b4[4] = {b4v.x, b4v.y, b4v.z, b4v.w};
        #pragma unroll
        for (int i = 0; i < 4; i++)
            #pragma unroll
            for (int j = 0; j < 4; j++)
                acc[i][j] += a4[i] * b4[j];
    }

    #pragma unroll
    for (int i = 0; i < 4; i++) {
        *(float4*)&sp[(size_t)(bi + (ty << 2) + i) * SS + bj + (tx << 2)] =
            make_float4(acc[i][0], acc[i][1], acc[i][2], acc[i][3]);
    }
}

// ---------------------------------------------------------------------------
// In-place row softmax over the last axis, then multiply by attention_bias
// (AFTER normalization, no renorm — matches reference). One block per row.
// ---------------------------------------------------------------------------
__global__ __launch_bounds__(256) void softmax_bias(
    float* __restrict__ scores, const float* __restrict__ bias)
{
    const int r = blockIdx.x;          // 0 .. B*H*S-1,  r = (b*H+h)*S + i
    const int i = r & (SS - 1);
    const int b = r >> 15;             // r / (H*S)
    float* row = scores + (size_t)r * SS;
    const float* brow = bias + ((size_t)b * SS + i) * SS;
    const int tid = threadIdx.x;
    __shared__ float red[8];

    float vals[8];
    float m = -1e30f;
    #pragma unroll
    for (int t = 0; t < 8; t++) { vals[t] = row[tid + (t << 8)]; m = fmaxf(m, vals[t]); }
    #pragma unroll
    for (int o = 16; o; o >>= 1) m = fmaxf(m, __shfl_xor_sync(0xffffffffu, m, o));
    if ((tid & 31) == 0) red[tid >> 5] = m;
    __syncthreads();
    float mm = red[0];
    #pragma unroll
    for (int w = 1; w < 8; w++) mm = fmaxf(mm, red[w]);
    __syncthreads();

    float s = 0.f;
    #pragma unroll
    for (int t = 0; t < 8; t++) { vals[t] = __expf(vals[t] - mm); s += vals[t]; }
    #pragma unroll
    for (int o = 16; o; o >>= 1) s += __shfl_xor_sync(0xffffffffu, s, o);
    if ((tid & 31) == 0) red[tid >> 5] = s;
    __syncthreads();
    float tot = 0.f;
    #pragma unroll
    for (int w = 0; w < 8; w++) tot += red[w];
    float inv = 1.0f / tot;

    #pragma unroll
    for (int t = 0; t < 8; t++)
        row[tid + (t << 8)] = vals[t] * inv * brow[tid + (t << 8)];
}

// ---------------------------------------------------------------------------
// out[b,i,h,:] = probs[z][i][:] @ v[b,:,h,:]   (M=S, N=64, K=S)
// ---------------------------------------------------------------------------
__global__ __launch_bounds__(256) void attn_pv(
    const float* __restrict__ scores, const float* __restrict__ v,
    float* __restrict__ outp)
{
    __shared__ float Ps[16][68];
    __shared__ float Vs[16][68];
    const int tid = threadIdx.x;
    const int tx = tid & 15, ty = tid >> 4;
    const int z = blockIdx.z;
    const int b = z >> 4, h = z & 15;
    const float* P  = scores + (size_t)z * SS * SS;
    const float* vp = v + (size_t)b * SS * HID + h * DD;
    float* op = outp + (size_t)b * SS * HID + h * DD;
    const int bi = blockIdx.y << 6;
    const int arow = tid >> 2, ak = (tid & 3) << 2;
    const int bk = tid >> 4, bn4 = (tid & 15) << 2;
    float acc[4][4] = {};

    for (int k0 = 0; k0 < SS; k0 += 16) {
        float4 av = *(const float4*)&P[(size_t)(bi + arow) * SS + k0 + ak];
        float4 bv = *(const float4*)&vp[(size_t)(k0 + bk) * HID + bn4];
        Ps[ak+0][arow] = av.x; Ps[ak+1][arow] = av.y;
        Ps[ak+2][arow] = av.z; Ps[ak+3][arow] = av.w;
        *(float4*)&Vs[bk][bn4] = bv;
        __syncthreads();
        #pragma unroll
        for (int kk = 0; kk < 16; kk++) {
            float4 a = *(const float4*)&Ps[kk][ty << 2];
            float4 b4v = *(const float4*)&Vs[kk][tx << 2];
            float a4[4] = {a.x, a.y, a.z, a.w};
            float b4[4] = {b4v.x, b4v.y, b4v.z, b4v.w};
            #pragma unroll
            for (int i = 0; i < 4; i++)
                #pragma unroll
                for (int j = 0; j < 4; j++)
                    acc[i][j] += a4[i] * b4[j];
        }
        __syncthreads();
    }

    #pragma unroll
    for (int i = 0; i < 4; i++) {
        *(float4*)&op[(size_t)(bi + (ty << 2) + i) * HID + (tx << 2)] =
            make_float4(acc[i][0], acc[i][1], acc[i][2], acc[i][3]);
    }
}

// ---------------------------------------------------------------------------
extern "C" void kernel_launch(void* const* d_in, const int* in_sizes, int n_in,
                              void* d_out, int out_size)
{
    const float* x     = (const float*)d_in[0];
    const float* sinu  = (const float*)d_in[1];
    const float* abias = (const float*)d_in[2];
    const float* Wq    = (const float*)d_in[3];
    const float* bq    = (const float*)d_in[4];
    const float* Wk    = (const float*)d_in[5];
    const float* bk    = (const float*)d_in[6];
    const float* Wv    = (const float*)d_in[7];
    const float* bv    = (const float*)d_in[8];
    const float* Wo    = (const float*)d_in[9];
    float* out = (float*)d_out;

    float *q, *k, *v, *attn, *sc;
    cudaGetSymbolAddress((void**)&q,    g_q);
    cudaGetSymbolAddress((void**)&k,    g_k);
    cudaGetSymbolAddress((void**)&v,    g_v);
    cudaGetSymbolAddress((void**)&attn, g_attn);
    cudaGetSymbolAddress((void**)&sc,   g_scores);

    dim3 blk(256);
    dim3 gproj(HID / 64, MTOT / 64);

    sgemm_nn<<<gproj, blk>>>(x, Wq, bq, q, MTOT, HID, HID);
    sgemm_nn<<<gproj, blk>>>(x, Wk, bk, k, MTOT, HID, HID);
    sgemm_nn<<<gproj, blk>>>(x, Wv, bv, v, MTOT, HID, HID);

    rotary_scale<<<MTOT * HID / 256, blk>>>(q, k, sinu);

    attn_scores<<<dim3(SS / 64, SS / 64, BB * HH), blk>>>(q, k, sc);
    softmax_bias<<<BB * HH * SS, blk>>>(sc, abias);
    attn_pv<<<dim3(1, SS / 64, BB * HH), blk>>>(sc, v, attn);

    sgemm_nn<<<gproj, blk>>>(attn, Wo, nullptr, out, MTOT, HID, HID);
}

// round 10
// speedup vs baseline: 2.5014x; 2.5014x over previous
#include <cuda_runtime.h>
#include <cuda_bf16.h>
#include <math.h>
#include <stdint.h>

#define BB   2
#define SS   2048
#define HID  1024
#define HH   16
#define DD   64
#define ROTD 32
#define MTOT (BB*SS)
#define NELEM ((size_t)MTOT*HID)

// ---------------- scratch (allocation-free rule) : ~96 MB total -------------
__device__ __nv_bfloat16 g_xhi[NELEM],  g_xlo[NELEM];
__device__ __nv_bfloat16 g_qhi[NELEM],  g_qlo[NELEM];
__device__ __nv_bfloat16 g_khi[NELEM],  g_klo[NELEM];
__device__ __nv_bfloat16 g_vthi[NELEM], g_vtlo[NELEM];   // [b*HID+d][s]
__device__ __nv_bfloat16 g_ahi[NELEM],  g_alo[NELEM];
__device__ __nv_bfloat16 g_wh[4][HID*HID], g_wl[4][HID*HID]; // WT[n][k] q,k,v,o

// ---------------------------------------------------------------------------
__device__ __forceinline__ void mma_bf16(float* d, const uint32_t* a, const uint32_t* b) {
    asm volatile(
        "mma.sync.aligned.m16n8k16.row.col.f32.bf16.bf16.f32 "
        "{%0,%1,%2,%3}, {%4,%5,%6,%7}, {%8,%9}, {%0,%1,%2,%3};"
        : "+f"(d[0]), "+f"(d[1]), "+f"(d[2]), "+f"(d[3])
        : "r"(a[0]), "r"(a[1]), "r"(a[2]), "r"(a[3]), "r"(b[0]), "r"(b[1]));
}

__device__ __forceinline__ void bsplit(float v, __nv_bfloat16& h, __nv_bfloat16& l) {
    h = __float2bfloat16_rn(v);
    l = __float2bfloat16_rn(v - __bfloat162float(h));
}

// split two floats -> packed hi pair + packed lo pair
__device__ __forceinline__ void split2(float x0, float x1, uint32_t& hp, uint32_t& lp) {
    __nv_bfloat16 h0, l0, h1, l1;
    bsplit(x0, h0, l0); bsplit(x1, h1, l1);
    __nv_bfloat162 hh = __halves2bfloat162(h0, h1);
    __nv_bfloat162 ll = __halves2bfloat162(l0, l1);
    hp = *(uint32_t*)&hh; lp = *(uint32_t*)&ll;
}

__device__ __forceinline__ void cpa(uint32_t s, const void* g) {
    asm volatile("cp.async.cg.shared.global [%0], [%1], 16;" :: "r"(s), "l"(g));
}
__device__ __forceinline__ void cpa_commit() { asm volatile("cp.async.commit_group;"); }
__device__ __forceinline__ void cpa_wait()   { asm volatile("cp.async.wait_group 0;"); }

// rotary factors for (s, d0even, d0+1); f=1 outside rope region
__device__ __forceinline__ float2 rotf(const float* sinu, int b, int s, int d0) {
    if (d0 >= ROTD) return make_float2(1.f, 1.f);
    const float* sp = sinu + ((size_t)(b * 2) * SS + s) * ROTD;
    const float* cp = sp + (size_t)SS * ROTD;
    return make_float2(cp[d0] - sp[d0], cp[d0 + 1] + sp[d0 + 1]);
}

// ---------------------------------------------------------------------------
// Projection GEMM: C[4096,1024] = A[4096,1024] @ WT[1024,1024]^T (+bias).
// A,B split-bf16 (3 mma). 128x128 block, BK=32, 8 warps (4m x 2n),
// warp tile 32x64 (MT=2, NT=8). MODE: 0=fp32 out (Wo); 1=Q rot+scale+split;
// 2=K rot+split; 3=V split transposed to [b*HID+col][s].
// ---------------------------------------------------------------------------
template<int MODE>
__global__ __launch_bounds__(256) void gemm_proj(
    const __nv_bfloat16* __restrict__ Ahi, const __nv_bfloat16* __restrict__ Alo,
    const __nv_bfloat16* __restrict__ Bhi, const __nv_bfloat16* __restrict__ Blo,
    const float* __restrict__ bias, const float* __restrict__ sinu,
    float* __restrict__ Cf, __nv_bfloat16* __restrict__ Chi, __nv_bfloat16* __restrict__ Clo)
{
    constexpr int WS = 20, AW = 128 * WS;
    extern __shared__ uint32_t sm[];
    uint32_t* sAh = sm;             uint32_t* sAl = sm + 2 * AW;
    uint32_t* sBh = sm + 4 * AW;    uint32_t* sBl = sm + 6 * AW;

    const int tid = threadIdx.x, wid = tid >> 5, lane = tid & 31;
    const int g = lane >> 2, t4 = lane & 3;
    const int wm0 = (wid & 3) * 32, wn0 = (wid >> 2) * 64;
    const int bm = blockIdx.y << 7, bn = blockIdx.x << 7;

    const int ar = tid >> 1, ah = tid & 1;
    const size_t aoff = (size_t)(bm + ar) * HID + ah * 16;
    const size_t boff = (size_t)(bn + ar) * HID + ah * 16;

    uint4 pa[2][2], pb[2][2];
    float acc[2][8][4] = {};

    auto loadAB = [&](int k0) {
        pa[0][0] = *(const uint4*)(Ahi + aoff + k0); pa[0][1] = *(const uint4*)(Ahi + aoff + k0 + 8);
        pa[1][0] = *(const uint4*)(Alo + aoff + k0); pa[1][1] = *(const uint4*)(Alo + aoff + k0 + 8);
        pb[0][0] = *(const uint4*)(Bhi + boff + k0); pb[0][1] = *(const uint4*)(Bhi + boff + k0 + 8);
        pb[1][0] = *(const uint4*)(Blo + boff + k0); pb[1][1] = *(const uint4*)(Blo + boff + k0 + 8);
    };
    auto storeAB = [&](int buf) {
        uint32_t* d;
        d = sAh + buf * AW + ar * WS + ah * 8; *(uint4*)d = pa[0][0]; *(uint4*)(d + 4) = pa[0][1];
        d = sAl + buf * AW + ar * WS + ah * 8; *(uint4*)d = pa[1][0]; *(uint4*)(d + 4) = pa[1][1];
        d = sBh + buf * AW + ar * WS + ah * 8; *(uint4*)d = pb[0][0]; *(uint4*)(d + 4) = pb[0][1];
        d = sBl + buf * AW + ar * WS + ah * 8; *(uint4*)d = pb[1][0]; *(uint4*)(d + 4) = pb[1][1];
    };
    auto compute = [&](int buf) {
        const uint32_t* cAh = sAh + buf * AW; const uint32_t* cAl = sAl + buf * AW;
        const uint32_t* cBh = sBh + buf * AW; const uint32_t* cBl = sBl + buf * AW;
        #pragma unroll
        for (int ks = 0; ks < 2; ks++) {
            uint32_t fah[2][4], fal[2][4];
            #pragma unroll
            for (int mt = 0; mt < 2; mt++) {
                int w = (wm0 + mt * 16 + g) * WS + ks * 8 + t4;
                fah[mt][0] = cAh[w];     fah[mt][1] = cAh[w + 8 * WS];
                fah[mt][2] = cAh[w + 4]; fah[mt][3] = cAh[w + 8 * WS + 4];
                fal[mt][0] = cAl[w];     fal[mt][1] = cAl[w + 8 * WS];
                fal[mt][2] = cAl[w + 4]; fal[mt][3] = cAl[w + 8 * WS + 4];
            }
            #pragma unroll
            for (int nt = 0; nt < 8; nt++) {
                int wb = (wn0 + nt * 8 + g) * WS + ks * 8 + t4;
                uint32_t fbh[2] = { cBh[wb], cBh[wb + 4] };
                uint32_t fbl[2] = { cBl[wb], cBl[wb + 4] };
                #pragma unroll
                for (int mt = 0; mt < 2; mt++) {
                    mma_bf16(acc[mt][nt], fah[mt], fbh);
                    mma_bf16(acc[mt][nt], fah[mt], fbl);
                    mma_bf16(acc[mt][nt], fal[mt], fbh);
                }
            }
        }
    };

    loadAB(0); storeAB(0); __syncthreads();
    for (int it = 0; it < 32; ++it) {
        const int cur = it & 1;
        if (it + 1 < 32) loadAB((it + 1) << 5);
        compute(cur);
        if (it + 1 < 32) { storeAB(cur ^ 1); __syncthreads(); }
    }

    #pragma unroll
    for (int mt = 0; mt < 2; mt++) {
        #pragma unroll
        for (int nt = 0; nt < 8; nt++) {
            const int row = bm + wm0 + mt * 16 + g;
            const int col = bn + wn0 + nt * 8 + 2 * t4;
            float c0 = acc[mt][nt][0], c1 = acc[mt][nt][1];
            float c2 = acc[mt][nt][2], c3 = acc[mt][nt][3];
            if (MODE == 0) {
                *(float2*)&Cf[(size_t)row * HID + col] = make_float2(c0, c1);
                *(float2*)&Cf[(size_t)(row + 8) * HID + col] = make_float2(c2, c3);
                continue;
            }
            const float b0 = bias[col], b1 = bias[col + 1];
            c0 += b0; c1 += b1; c2 += b0; c3 += b1;
            const int bidx = row >> 11, s0 = row & (SS - 1), s1 = (row + 8) & (SS - 1);
            if (MODE == 1 || MODE == 2) {
                const int d0 = col & 63;
                float2 f0 = rotf(sinu, bidx, s0, d0);
                float2 f1 = rotf(sinu, bidx, s1, d0);
                const float qs = (MODE == 1) ? 0.125f : 1.0f;
                c0 *= f0.x * qs; c1 *= f0.y * qs;
                c2 *= f1.x * qs; c3 *= f1.y * qs;
                uint32_t hp, lp;
                split2(c0, c1, hp, lp);
                *(uint32_t*)&Chi[(size_t)row * HID + col] = hp;
                *(uint32_t*)&Clo[(size_t)row * HID + col] = lp;
                split2(c2, c3, hp, lp);
                *(uint32_t*)&Chi[(size_t)(row + 8) * HID + col] = hp;
                *(uint32_t*)&Clo[(size_t)(row + 8) * HID + col] = lp;
            } else {  // MODE 3 : V, transposed split store
                __nv_bfloat16 h, l;
                const size_t r0 = ((size_t)bidx * HID + col) * SS;
                const size_t r1 = ((size_t)bidx * HID + col + 1) * SS;
                bsplit(c0, h, l); Chi[r0 + s0] = h; Clo[r0 + s0] = l;
                bsplit(c1, h, l); Chi[r1 + s0] = h; Clo[r1 + s0] = l;
                bsplit(c2, h, l); Chi[r0 + s1] = h; Clo[r0 + s1] = l;
                bsplit(c3, h, l); Chi[r1 + s1] = h; Clo[r1 + s1] = l;
            }
        }
    }
}

// ---------------------------------------------------------------------------
// Fused flash attention: per block = one (b,h) + 128 query rows.
// online: Z = sum exp(s-m)  (bias-free);  O += exp(s-m)*bias * V ; out = O/Z.
// K tiles [key][d] stride 36 words; V tiles [d][s] stride 68 words.
// Double buffered via cp.async. 8 warps; warp = 16 q-rows;
// S warp tile 16x128 (NT=16), O tile 16x64 (8 n-tiles of 8).
// ---------------------------------------------------------------------------
#define KWORDS 4608   // 128 rows * 36 words
#define VWORDS 4352   // 64 rows * 68 words
#define SM_KH 0
#define SM_KL (2*KWORDS)
#define SM_VH (4*KWORDS)
#define SM_VL (4*KWORDS + 2*VWORDS)
#define SM_TOT_W (4*KWORDS + 4*VWORDS)   // 35840 words = 143360 B

__global__ __launch_bounds__(256, 1) void flash_attn(
    const __nv_bfloat16* __restrict__ qhi, const __nv_bfloat16* __restrict__ qlo,
    const __nv_bfloat16* __restrict__ khi, const __nv_bfloat16* __restrict__ klo,
    const __nv_bfloat16* __restrict__ vthi, const __nv_bfloat16* __restrict__ vtlo,
    const float* __restrict__ bias,
    __nv_bfloat16* __restrict__ ahi, __nv_bfloat16* __restrict__ alo)
{
    extern __shared__ uint32_t sm[];
    const uint32_t smb = (uint32_t)__cvta_generic_to_shared(sm);

    const int tid = threadIdx.x, wid = tid >> 5, lane = tid & 31;
    const int g = lane >> 2, t4 = lane & 3;
    const int bh = blockIdx.x, b = bh >> 4, h = bh & 15;
    const int qi0 = (blockIdx.y << 7) + wid * 16;     // this warp's first q row
    const int qrow = qi0 + g;

    // ---- Q fragments (registers, one-time) ----
    uint32_t qfh[4][4], qfl[4][4];
    {
        const size_t o0 = ((size_t)(b * SS + qrow)) * HID + h * DD;
        const size_t o1 = o0 + (size_t)8 * HID;
        #pragma unroll
        for (int c = 0; c < 4; c++) {
            const int k0 = c * 16 + 2 * t4;
            qfh[c][0] = *(const uint32_t*)&qhi[o0 + k0];
            qfh[c][1] = *(const uint32_t*)&qhi[o1 + k0];
            qfh[c][2] = *(const uint32_t*)&qhi[o0 + k0 + 8];
            qfh[c][3] = *(const uint32_t*)&qhi[o1 + k0 + 8];
            qfl[c][0] = *(const uint32_t*)&qlo[o0 + k0];
            qfl[c][1] = *(const uint32_t*)&qlo[o1 + k0];
            qfl[c][2] = *(const uint32_t*)&qlo[o0 + k0 + 8];
            qfl[c][3] = *(const uint32_t*)&qlo[o1 + k0 + 8];
        }
    }

    // tile loader (cp.async, 16 x 16B per thread)
    const int kr = tid >> 1, khalf = tid & 1;
    const int vd = tid >> 2, vq = tid & 3;
    auto load_tile = [&](int jt, int buf) {
        const int j0 = jt << 7;
        const size_t gko = ((size_t)(b * SS + j0 + kr)) * HID + h * DD + khalf * 32;
        uint32_t skh = smb + (SM_KH + buf * KWORDS + kr * 36 + khalf * 16) * 4;
        uint32_t skl = smb + (SM_KL + buf * KWORDS + kr * 36 + khalf * 16) * 4;
        #pragma unroll
        for (int u = 0; u < 4; u++) {
            cpa(skh + u * 16, khi + gko + u * 8);
            cpa(skl + u * 16, klo + gko + u * 8);
        }
        const size_t gvo = ((size_t)b * HID + h * DD + vd) * SS + j0 + vq * 32;
        uint32_t svh = smb + (SM_VH + buf * VWORDS + vd * 68 + vq * 16) * 4;
        uint32_t svl = smb + (SM_VL + buf * VWORDS + vd * 68 + vq * 16) * 4;
        #pragma unroll
        for (int u = 0; u < 4; u++) {
            cpa(svh + u * 16, vthi + gvo + u * 8);
            cpa(svl + u * 16, vtlo + gvo + u * 8);
        }
        cpa_commit();
    };

    float acc_o[8][4] = {};
    float m0 = -1e30f, m1 = -1e30f, z0 = 0.f, z1 = 0.f;
    const float* brow0 = bias + ((size_t)(b * SS + qrow)) * SS;
    const float* brow1 = brow0 + (size_t)8 * SS;

    load_tile(0, 0);

    for (int jt = 0; jt < SS / 128; ++jt) {
        const int buf = jt & 1;
        cpa_wait();
        __syncthreads();
        if (jt + 1 < SS / 128) load_tile(jt + 1, buf ^ 1);

        const uint32_t* cKh = sm + SM_KH + buf * KWORDS;
        const uint32_t* cKl = sm + SM_KL + buf * KWORDS;
        const uint32_t* cVh = sm + SM_VH + buf * VWORDS;
        const uint32_t* cVl = sm + SM_VL + buf * VWORDS;

        // ---- S = Q K^T  (16 n-tiles) ----
        float s[16][4];
        #pragma unroll
        for (int nt = 0; nt < 16; nt++) { s[nt][0] = s[nt][1] = s[nt][2] = s[nt][3] = 0.f; }
        #pragma unroll
        for (int c = 0; c < 4; c++) {
            #pragma unroll
            for (int nt = 0; nt < 16; nt++) {
                const int wb = (nt * 8 + g) * 36 + c * 8 + t4;
                uint32_t bhf[2] = { cKh[wb], cKh[wb + 4] };
                uint32_t blf[2] = { cKl[wb], cKl[wb + 4] };
                mma_bf16(s[nt], qfh[c], bhf);
                mma_bf16(s[nt], qfh[c], blf);
                mma_bf16(s[nt], qfl[c], bhf);
            }
        }

        // ---- online softmax (Z bias-free), fold bias into P ----
        const int j0 = jt << 7;
        float tm0 = -1e30f, tm1 = -1e30f;
        #pragma unroll
        for (int nt = 0; nt < 16; nt++) {
            tm0 = fmaxf(tm0, fmaxf(s[nt][0], s[nt][1]));
            tm1 = fmaxf(tm1, fmaxf(s[nt][2], s[nt][3]));
        }
        tm0 = fmaxf(tm0, __shfl_xor_sync(0xffffffffu, tm0, 1));
        tm0 = fmaxf(tm0, __shfl_xor_sync(0xffffffffu, tm0, 2));
        tm1 = fmaxf(tm1, __shfl_xor_sync(0xffffffffu, tm1, 1));
        tm1 = fmaxf(tm1, __shfl_xor_sync(0xffffffffu, tm1, 2));
        const float mn0 = fmaxf(m0, tm0), mn1 = fmaxf(m1, tm1);
        const float sc0 = __expf(m0 - mn0), sc1 = __expf(m1 - mn1);
        m0 = mn0; m1 = mn1;

        float ps0 = 0.f, ps1 = 0.f;
        #pragma unroll
        for (int nt = 0; nt < 16; nt++) {
            const int jc = j0 + nt * 8 + 2 * t4;
            float2 bb0 = *(const float2*)&brow0[jc];
            float2 bb1 = *(const float2*)&brow1[jc];
            float p0 = __expf(s[nt][0] - mn0), p1 = __expf(s[nt][1] - mn0);
            float p2 = __expf(s[nt][2] - mn1), p3 = __expf(s[nt][3] - mn1);
            ps0 += p0 + p1; ps1 += p2 + p3;
            s[nt][0] = p0 * bb0.x; s[nt][1] = p1 * bb0.y;
            s[nt][2] = p2 * bb1.x; s[nt][3] = p3 * bb1.y;
        }
        ps0 += __shfl_xor_sync(0xffffffffu, ps0, 1);
        ps0 += __shfl_xor_sync(0xffffffffu, ps0, 2);
        ps1 += __shfl_xor_sync(0xffffffffu, ps1, 1);
        ps1 += __shfl_xor_sync(0xffffffffu, ps1, 2);
        z0 = z0 * sc0 + ps0;
        z1 = z1 * sc1 + ps1;

        // rescale O (all 8 d-tiles)
        #pragma unroll
        for (int dt = 0; dt < 8; dt++) {
            acc_o[dt][0] *= sc0; acc_o[dt][1] *= sc0;
            acc_o[dt][2] *= sc1; acc_o[dt][3] *= sc1;
        }

        // ---- O += P V  (P from registers, split; 8 d-tiles = 64 cols) ----
        #pragma unroll
        for (int cc = 0; cc < 8; cc++) {
            uint32_t Ah[4], Al[4];
            split2(s[2 * cc][0],     s[2 * cc][1],     Ah[0], Al[0]);
            split2(s[2 * cc][2],     s[2 * cc][3],     Ah[1], Al[1]);
            split2(s[2 * cc + 1][0], s[2 * cc + 1][1], Ah[2], Al[2]);
            split2(s[2 * cc + 1][2], s[2 * cc + 1][3], Ah[3], Al[3]);
            #pragma unroll
            for (int dt = 0; dt < 8; dt++) {
                const int wb = (dt * 8 + g) * 68 + cc * 8 + t4;
                uint32_t vh[2] = { cVh[wb], cVh[wb + 4] };
                uint32_t vl[2] = { cVl[wb], cVl[wb + 4] };
                mma_bf16(acc_o[dt], Ah, vh);
                mma_bf16(acc_o[dt], Al, vh);
                mma_bf16(acc_o[dt], Ah, vl);
            }
        }
    }

    // ---- epilogue: O/Z, split-bf16 store (full 64 cols) ----
    const float i0 = 1.0f / z0, i1 = 1.0f / z1;
    #pragma unroll
    for (int dt = 0; dt < 8; dt++) {
        const int col = h * DD + dt * 8 + 2 * t4;
        const size_t o0 = ((size_t)(b * SS + qrow)) * HID + col;
        const size_t o1 = o0 + (size_t)8 * HID;
        uint32_t hp, lp;
        split2(acc_o[dt][0] * i0, acc_o[dt][1] * i0, hp, lp);
        *(uint32_t*)&ahi[o0] = hp; *(uint32_t*)&alo[o0] = lp;
        split2(acc_o[dt][2] * i1, acc_o[dt][3] * i1, hp, lp);
        *(uint32_t*)&ahi[o1] = hp; *(uint32_t*)&alo[o1] = lp;
    }
}

// ---------------------------------------------------------------------------
__global__ __launch_bounds__(256) void split_x(
    const float* __restrict__ in, __nv_bfloat16* __restrict__ hi,
    __nv_bfloat16* __restrict__ lo)
{
    size_t i4 = (size_t)blockIdx.x * 256 + threadIdx.x;
    float4 v = ((const float4*)in)[i4];
    uint32_t h0, l0, h1, l1;
    split2(v.x, v.y, h0, l0);
    split2(v.z, v.w, h1, l1);
    ((uint32_t*)hi)[i4 * 2] = h0; ((uint32_t*)lo)[i4 * 2] = l0;
    ((uint32_t*)hi)[i4 * 2 + 1] = h1; ((uint32_t*)lo)[i4 * 2 + 1] = l1;
}

__global__ void trans_w(const float* __restrict__ W,
                        __nv_bfloat16* __restrict__ Thi, __nv_bfloat16* __restrict__ Tlo)
{
    __shared__ float ts[32][33];
    const int n0 = blockIdx.x * 32, k0 = blockIdx.y * 32;
    const int tx = threadIdx.x, ty = threadIdx.y;
    #pragma unroll
    for (int i = 0; i < 4; i++)
        ts[ty + 8 * i][tx] = W[(size_t)(k0 + ty + 8 * i) * HID + n0 + tx];
    __syncthreads();
    #pragma unroll
    for (int i = 0; i < 4; i++) {
        __nv_bfloat16 h, l; bsplit(ts[tx][ty + 8 * i], h, l);
        size_t o = (size_t)(n0 + ty + 8 * i) * HID + k0 + tx;
        Thi[o] = h; Tlo[o] = l;
    }
}

// ---------------------------------------------------------------------------
extern "C" void kernel_launch(void* const* d_in, const int* in_sizes, int n_in,
                              void* d_out, int out_size)
{
    const float* x     = (const float*)d_in[0];
    const float* sinu  = (const float*)d_in[1];
    const float* abias = (const float*)d_in[2];
    const float* Wq    = (const float*)d_in[3];
    const float* bq    = (const float*)d_in[4];
    const float* Wk    = (const float*)d_in[5];
    const float* bk    = (const float*)d_in[6];
    const float* Wv    = (const float*)d_in[7];
    const float* bv    = (const float*)d_in[8];
    const float* Wo    = (const float*)d_in[9];
    float* out = (float*)d_out;

    __nv_bfloat16 *xhi, *xlo, *qhi, *qlo, *khi, *klo, *vthi, *vtlo, *ahi, *alo, *wh, *wl;
    cudaGetSymbolAddress((void**)&xhi, g_xhi);   cudaGetSymbolAddress((void**)&xlo, g_xlo);
    cudaGetSymbolAddress((void**)&qhi, g_qhi);   cudaGetSymbolAddress((void**)&qlo, g_qlo);
    cudaGetSymbolAddress((void**)&khi, g_khi);   cudaGetSymbolAddress((void**)&klo, g_klo);
    cudaGetSymbolAddress((void**)&vthi, g_vthi); cudaGetSymbolAddress((void**)&vtlo, g_vtlo);
    cudaGetSymbolAddress((void**)&ahi, g_ahi);   cudaGetSymbolAddress((void**)&alo, g_alo);
    cudaGetSymbolAddress((void**)&wh, g_wh);     cudaGetSymbolAddress((void**)&wl, g_wl);

    cudaFuncSetAttribute(gemm_proj<0>, cudaFuncAttributeMaxDynamicSharedMemorySize, 81920);
    cudaFuncSetAttribute(gemm_proj<1>, cudaFuncAttributeMaxDynamicSharedMemorySize, 81920);
    cudaFuncSetAttribute(gemm_proj<2>, cudaFuncAttributeMaxDynamicSharedMemorySize, 81920);
    cudaFuncSetAttribute(gemm_proj<3>, cudaFuncAttributeMaxDynamicSharedMemorySize, 81920);
    cudaFuncSetAttribute(flash_attn,   cudaFuncAttributeMaxDynamicSharedMemorySize, SM_TOT_W * 4);

    dim3 blk(256);
    const int WSZ = HID * HID;

    split_x<<<(int)(NELEM / 4 / 256), blk>>>(x, xhi, xlo);
    trans_w<<<dim3(32, 32), dim3(32, 8)>>>(Wq, wh + 0 * WSZ, wl + 0 * WSZ);
    trans_w<<<dim3(32, 32), dim3(32, 8)>>>(Wk, wh + 1 * WSZ, wl + 1 * WSZ);
    trans_w<<<dim3(32, 32), dim3(32, 8)>>>(Wv, wh + 2 * WSZ, wl + 2 * WSZ);
    trans_w<<<dim3(32, 32), dim3(32, 8)>>>(Wo, wh + 3 * WSZ, wl + 3 * WSZ);

    dim3 gproj(HID / 128, MTOT / 128);
    gemm_proj<1><<<gproj, blk, 81920>>>(xhi, xlo, wh + 0 * WSZ, wl + 0 * WSZ, bq, sinu,
                                        nullptr, qhi, qlo);
    gemm_proj<2><<<gproj, blk, 81920>>>(xhi, xlo, wh + 1 * WSZ, wl + 1 * WSZ, bk, sinu,
                                        nullptr, khi, klo);
    gemm_proj<3><<<gproj, blk, 81920>>>(xhi, xlo, wh + 2 * WSZ, wl + 2 * WSZ, bv, nullptr,
                                        nullptr, vthi, vtlo);

    flash_attn<<<dim3(BB * HH, SS / 128), blk, SM_TOT_W * 4>>>(
        qhi, qlo, khi, klo, vthi, vtlo, abias, ahi, alo);

    gemm_proj<0><<<gproj, blk, 81920>>>(ahi, alo, wh + 3 * WSZ, wl + 3 * WSZ, nullptr, nullptr,
                                        out, nullptr, nullptr);
}

// round 16
// speedup vs baseline: 2.6616x; 1.0640x over previous
#include <cuda_runtime.h>
#include <cuda_bf16.h>
#include <math.h>
#include <stdint.h>

#define BB   2
#define SS   2048
#define HID  1024
#define HH   16
#define DD   64
#define ROTD 32
#define MTOT (BB*SS)
#define NELEM ((size_t)MTOT*HID)

// ---------------- scratch (allocation-free rule) : ~96 MB total -------------
__device__ __nv_bfloat16 g_xhi[NELEM],  g_xlo[NELEM];
__device__ __nv_bfloat16 g_qhi[NELEM],  g_qlo[NELEM];
__device__ __nv_bfloat16 g_khi[NELEM],  g_klo[NELEM];
__device__ __nv_bfloat16 g_vthi[NELEM], g_vtlo[NELEM];   // [b*HID+d][s]
__device__ __nv_bfloat16 g_ahi[NELEM],  g_alo[NELEM];
__device__ __nv_bfloat16 g_wh[4][HID*HID], g_wl[4][HID*HID]; // WT[n][k] q,k,v,o

// ---------------------------------------------------------------------------
__device__ __forceinline__ void mma_bf16(float* d, const uint32_t* a, const uint32_t* b) {
    asm volatile(
        "mma.sync.aligned.m16n8k16.row.col.f32.bf16.bf16.f32 "
        "{%0,%1,%2,%3}, {%4,%5,%6,%7}, {%8,%9}, {%0,%1,%2,%3};"
        : "+f"(d[0]), "+f"(d[1]), "+f"(d[2]), "+f"(d[3])
        : "r"(a[0]), "r"(a[1]), "r"(a[2]), "r"(a[3]), "r"(b[0]), "r"(b[1]));
}

// ldmatrix x4: four 8x8 b16 matrices; lane supplies one row address.
__device__ __forceinline__ void ldsm4(uint32_t* r, uint32_t saddr) {
    asm volatile("ldmatrix.sync.aligned.m8n8.x4.shared.b16 {%0,%1,%2,%3}, [%4];"
        : "=r"(r[0]), "=r"(r[1]), "=r"(r[2]), "=r"(r[3]) : "r"(saddr));
}

__device__ __forceinline__ void bsplit(float v, __nv_bfloat16& h, __nv_bfloat16& l) {
    h = __float2bfloat16_rn(v);
    l = __float2bfloat16_rn(v - __bfloat162float(h));
}

__device__ __forceinline__ void split2(float x0, float x1, uint32_t& hp, uint32_t& lp) {
    __nv_bfloat16 h0, l0, h1, l1;
    bsplit(x0, h0, l0); bsplit(x1, h1, l1);
    __nv_bfloat162 hh = __halves2bfloat162(h0, h1);
    __nv_bfloat162 ll = __halves2bfloat162(l0, l1);
    hp = *(uint32_t*)&hh; lp = *(uint32_t*)&ll;
}

__device__ __forceinline__ void cpa(uint32_t s, const void* g) {
    asm volatile("cp.async.cg.shared.global [%0], [%1], 16;" :: "r"(s), "l"(g));
}
__device__ __forceinline__ void cpa_commit() { asm volatile("cp.async.commit_group;"); }
__device__ __forceinline__ void cpa_wait()   { asm volatile("cp.async.wait_group 0;"); }

// rotary factors for (s, d0even, d0+1); f=1 outside rope region
__device__ __forceinline__ float2 rotf(const float* sinu, int b, int s, int d0) {
    if (d0 >= ROTD) return make_float2(1.f, 1.f);
    const float* sp = sinu + ((size_t)(b * 2) * SS + s) * ROTD;
    const float* cp = sp + (size_t)SS * ROTD;
    return make_float2(cp[d0] - sp[d0], cp[d0 + 1] + sp[d0 + 1]);
}

// ---------------------------------------------------------------------------
// Projection GEMM: C[4096,1024] = A[4096,1024] @ WT[1024,1024]^T (+bias).
// A,B split-bf16 (3 mma). 128x128 block, BK=32, 8 warps (4m x 2n),
// warp tile 32x64 (MT=2, NT=8). Fragments via ldmatrix.x4.
// MODE: 0=fp32 out (Wo); 1=Q rot+scale+split; 2=K rot+split; 3=V transp split.
// ---------------------------------------------------------------------------
template<int MODE>
__global__ __launch_bounds__(256) void gemm_proj(
    const __nv_bfloat16* __restrict__ Ahi, const __nv_bfloat16* __restrict__ Alo,
    const __nv_bfloat16* __restrict__ Bhi, const __nv_bfloat16* __restrict__ Blo,
    const float* __restrict__ bias, const float* __restrict__ sinu,
    float* __restrict__ Cf, __nv_bfloat16* __restrict__ Chi, __nv_bfloat16* __restrict__ Clo)
{
    constexpr int WS = 20, AW = 128 * WS;
    extern __shared__ uint32_t sm[];
    const uint32_t smb = (uint32_t)__cvta_generic_to_shared(sm);
    uint32_t* sAh = sm;             uint32_t* sAl = sm + 2 * AW;
    uint32_t* sBh = sm + 4 * AW;    uint32_t* sBl = sm + 6 * AW;

    const int tid = threadIdx.x, wid = tid >> 5, lane = tid & 31;
    const int g = lane >> 2, t4 = lane & 3;
    const int wm0 = (wid & 3) * 32, wn0 = (wid >> 2) * 64;
    const int bm = blockIdx.y << 7, bn = blockIdx.x << 7;

    // ldmatrix lane-address components
    const int am15 = lane & 15;                       // A: row within m16
    const int ak4  = (lane >> 4) << 2;                // A: k-half (words)
    const int br8  = ((lane >> 4) << 3) + (lane & 7); // B: row within n16 pair
    const int bk4  = ((lane >> 3) & 1) << 2;          // B: k-half (words)

    const int ar = tid >> 1, ah = tid & 1;
    const size_t aoff = (size_t)(bm + ar) * HID + ah * 16;
    const size_t boff = (size_t)(bn + ar) * HID + ah * 16;

    uint4 pa[2][2], pb[2][2];
    float acc[2][8][4] = {};

    auto loadAB = [&](int k0) {
        pa[0][0] = *(const uint4*)(Ahi + aoff + k0); pa[0][1] = *(const uint4*)(Ahi + aoff + k0 + 8);
        pa[1][0] = *(const uint4*)(Alo + aoff + k0); pa[1][1] = *(const uint4*)(Alo + aoff + k0 + 8);
        pb[0][0] = *(const uint4*)(Bhi + boff + k0); pb[0][1] = *(const uint4*)(Bhi + boff + k0 + 8);
        pb[1][0] = *(const uint4*)(Blo + boff + k0); pb[1][1] = *(const uint4*)(Blo + boff + k0 + 8);
    };
    auto storeAB = [&](int buf) {
        uint32_t* d;
        d = sAh + buf * AW + ar * WS + ah * 8; *(uint4*)d = pa[0][0]; *(uint4*)(d + 4) = pa[0][1];
        d = sAl + buf * AW + ar * WS + ah * 8; *(uint4*)d = pa[1][0]; *(uint4*)(d + 4) = pa[1][1];
        d = sBh + buf * AW + ar * WS + ah * 8; *(uint4*)d = pb[0][0]; *(uint4*)(d + 4) = pb[0][1];
        d = sBl + buf * AW + ar * WS + ah * 8; *(uint4*)d = pb[1][0]; *(uint4*)(d + 4) = pb[1][1];
    };
    auto compute = [&](int buf) {
        const uint32_t oAh = (uint32_t)((0 + buf) * AW) * 4;
        const uint32_t oAl = (uint32_t)((2 + buf) * AW) * 4;
        const uint32_t oBh = (uint32_t)((4 + buf) * AW) * 4;
        const uint32_t oBl = (uint32_t)((6 + buf) * AW) * 4;
        #pragma unroll
        for (int ks = 0; ks < 2; ks++) {
            uint32_t fah[2][4], fal[2][4];
            #pragma unroll
            for (int mt = 0; mt < 2; mt++) {
                const uint32_t w = (uint32_t)((wm0 + mt * 16 + am15) * WS + ks * 8 + ak4) * 4;
                ldsm4(fah[mt], smb + oAh + w);
                ldsm4(fal[mt], smb + oAl + w);
            }
            #pragma unroll
            for (int p = 0; p < 4; p++) {
                const uint32_t w = (uint32_t)((wn0 + p * 16 + br8) * WS + ks * 8 + bk4) * 4;
                uint32_t fbh[4], fbl[4];
                ldsm4(fbh, smb + oBh + w);
                ldsm4(fbl, smb + oBl + w);
                #pragma unroll
                for (int mt = 0; mt < 2; mt++) {
                    mma_bf16(acc[mt][2 * p],     fah[mt], fbh);
                    mma_bf16(acc[mt][2 * p],     fah[mt], fbl);
                    mma_bf16(acc[mt][2 * p],     fal[mt], fbh);
                    mma_bf16(acc[mt][2 * p + 1], fah[mt], fbh + 2);
                    mma_bf16(acc[mt][2 * p + 1], fah[mt], fbl + 2);
                    mma_bf16(acc[mt][2 * p + 1], fal[mt], fbh + 2);
                }
            }
        }
    };

    loadAB(0); storeAB(0); __syncthreads();
    for (int it = 0; it < 32; ++it) {
        const int cur = it & 1;
        if (it + 1 < 32) loadAB((it + 1) << 5);
        compute(cur);
        if (it + 1 < 32) { storeAB(cur ^ 1); __syncthreads(); }
    }

    #pragma unroll
    for (int mt = 0; mt < 2; mt++) {
        #pragma unroll
        for (int nt = 0; nt < 8; nt++) {
            const int row = bm + wm0 + mt * 16 + g;
            const int col = bn + wn0 + nt * 8 + 2 * t4;
            float c0 = acc[mt][nt][0], c1 = acc[mt][nt][1];
            float c2 = acc[mt][nt][2], c3 = acc[mt][nt][3];
            if (MODE == 0) {
                *(float2*)&Cf[(size_t)row * HID + col] = make_float2(c0, c1);
                *(float2*)&Cf[(size_t)(row + 8) * HID + col] = make_float2(c2, c3);
                continue;
            }
            const float b0 = bias[col], b1 = bias[col + 1];
            c0 += b0; c1 += b1; c2 += b0; c3 += b1;
            const int bidx = row >> 11, s0 = row & (SS - 1), s1 = (row + 8) & (SS - 1);
            if (MODE == 1 || MODE == 2) {
                const int d0 = col & 63;
                float2 f0 = rotf(sinu, bidx, s0, d0);
                float2 f1 = rotf(sinu, bidx, s1, d0);
                const float qs = (MODE == 1) ? 0.125f : 1.0f;
                c0 *= f0.x * qs; c1 *= f0.y * qs;
                c2 *= f1.x * qs; c3 *= f1.y * qs;
                uint32_t hp, lp;
                split2(c0, c1, hp, lp);
                *(uint32_t*)&Chi[(size_t)row * HID + col] = hp;
                *(uint32_t*)&Clo[(size_t)row * HID + col] = lp;
                split2(c2, c3, hp, lp);
                *(uint32_t*)&Chi[(size_t)(row + 8) * HID + col] = hp;
                *(uint32_t*)&Clo[(size_t)(row + 8) * HID + col] = lp;
            } else {  // MODE 3 : V, transposed split store
                __nv_bfloat16 h, l;
                const size_t r0 = ((size_t)bidx * HID + col) * SS;
                const size_t r1 = ((size_t)bidx * HID + col + 1) * SS;
                bsplit(c0, h, l); Chi[r0 + s0] = h; Clo[r0 + s0] = l;
                bsplit(c1, h, l); Chi[r1 + s0] = h; Clo[r1 + s0] = l;
                bsplit(c2, h, l); Chi[r0 + s1] = h; Clo[r0 + s1] = l;
                bsplit(c3, h, l); Chi[r1 + s1] = h; Clo[r1 + s1] = l;
            }
        }
    }
}

// ---------------------------------------------------------------------------
// Fused flash attention: per block = one (b,h) + 128 query rows.
// online: Z = sum exp(s-m)  (bias-free);  O += exp(s-m)*bias * V ; out = O/Z.
// K tiles [key][d] stride 36 words; V tiles [d][s] stride 68 words.
// Double buffered via cp.async. 8 warps; warp = 16 q-rows.
// Fragments via ldmatrix.x4 (two n8-tiles per load).
// ---------------------------------------------------------------------------
#define KWORDS 4608
#define VWORDS 4352
#define SM_KH 0
#define SM_KL (2*KWORDS)
#define SM_VH (4*KWORDS)
#define SM_VL (4*KWORDS + 2*VWORDS)
#define SM_TOT_W (4*KWORDS + 4*VWORDS)

__global__ __launch_bounds__(256, 1) void flash_attn(
    const __nv_bfloat16* __restrict__ qhi, const __nv_bfloat16* __restrict__ qlo,
    const __nv_bfloat16* __restrict__ khi, const __nv_bfloat16* __restrict__ klo,
    const __nv_bfloat16* __restrict__ vthi, const __nv_bfloat16* __restrict__ vtlo,
    const float* __restrict__ bias,
    __nv_bfloat16* __restrict__ ahi, __nv_bfloat16* __restrict__ alo)
{
    extern __shared__ uint32_t sm[];
    const uint32_t smb = (uint32_t)__cvta_generic_to_shared(sm);

    const int tid = threadIdx.x, wid = tid >> 5, lane = tid & 31;
    const int g = lane >> 2, t4 = lane & 3;
    const int bh = blockIdx.x, b = bh >> 4, h = bh & 15;
    const int qi0 = (blockIdx.y << 7) + wid * 16;
    const int qrow = qi0 + g;

    const int br8 = ((lane >> 4) << 3) + (lane & 7);
    const int bk4 = ((lane >> 3) & 1) << 2;

    uint32_t qfh[4][4], qfl[4][4];
    {
        const size_t o0 = ((size_t)(b * SS + qrow)) * HID + h * DD;
        const size_t o1 = o0 + (size_t)8 * HID;
        #pragma unroll
        for (int c = 0; c < 4; c++) {
            const int k0 = c * 16 + 2 * t4;
            qfh[c][0] = *(const uint32_t*)&qhi[o0 + k0];
            qfh[c][1] = *(const uint32_t*)&qhi[o1 + k0];
            qfh[c][2] = *(const uint32_t*)&qhi[o0 + k0 + 8];
            qfh[c][3] = *(const uint32_t*)&qhi[o1 + k0 + 8];
            qfl[c][0] = *(const uint32_t*)&qlo[o0 + k0];
            qfl[c][1] = *(const uint32_t*)&qlo[o1 + k0];
            qfl[c][2] = *(const uint32_t*)&qlo[o0 + k0 + 8];
            qfl[c][3] = *(const uint32_t*)&qlo[o1 + k0 + 8];
        }
    }

    const int kr = tid >> 1, khalf = tid & 1;
    const int vd = tid >> 2, vq = tid & 3;
    auto load_tile = [&](int jt, int buf) {
        const int j0 = jt << 7;
        const size_t gko = ((size_t)(b * SS + j0 + kr)) * HID + h * DD + khalf * 32;
        uint32_t skh = smb + (SM_KH + buf * KWORDS + kr * 36 + khalf * 16) * 4;
        uint32_t skl = smb + (SM_KL + buf * KWORDS + kr * 36 + khalf * 16) * 4;
        #pragma unroll
        for (int u = 0; u < 4; u++) {
            cpa(skh + u * 16, khi + gko + u * 8);
            cpa(skl + u * 16, klo + gko + u * 8);
        }
        const size_t gvo = ((size_t)b * HID + h * DD + vd) * SS + j0 + vq * 32;
        uint32_t svh = smb + (SM_VH + buf * VWORDS + vd * 68 + vq * 16) * 4;
        uint32_t svl = smb + (SM_VL + buf * VWORDS + vd * 68 + vq * 16) * 4;
        #pragma unroll
        for (int u = 0; u < 4; u++) {
            cpa(svh + u * 16, vthi + gvo + u * 8);
            cpa(svl + u * 16, vtlo + gvo + u * 8);
        }
        cpa_commit();
    };

    float acc_o[8][4] = {};
    float m0 = -1e30f, m1 = -1e30f, z0 = 0.f, z1 = 0.f;
    const float* brow0 = bias + ((size_t)(b * SS + qrow)) * SS;
    const float* brow1 = brow0 + (size_t)8 * SS;

    load_tile(0, 0);

    for (int jt = 0; jt < SS / 128; ++jt) {
        const int buf = jt & 1;
        cpa_wait();
        __syncthreads();
        if (jt + 1 < SS / 128) load_tile(jt + 1, buf ^ 1);

        const uint32_t oKH = (uint32_t)(SM_KH + buf * KWORDS) * 4;
        const uint32_t oKL = (uint32_t)(SM_KL + buf * KWORDS) * 4;
        const uint32_t oVH = (uint32_t)(SM_VH + buf * VWORDS) * 4;
        const uint32_t oVL = (uint32_t)(SM_VL + buf * VWORDS) * 4;

        // ---- S = Q K^T  (8 ldsm pairs -> 16 n-tiles) ----
        float s[16][4];
        #pragma unroll
        for (int nt = 0; nt < 16; nt++) { s[nt][0] = s[nt][1] = s[nt][2] = s[nt][3] = 0.f; }
        #pragma unroll
        for (int c = 0; c < 4; c++) {
            #pragma unroll
            for (int p = 0; p < 8; p++) {
                const uint32_t w = (uint32_t)((p * 16 + br8) * 36 + c * 8 + bk4) * 4;
                uint32_t fbh[4], fbl[4];
                ldsm4(fbh, smb + oKH + w);
                ldsm4(fbl, smb + oKL + w);
                mma_bf16(s[2 * p],     qfh[c], fbh);
                mma_bf16(s[2 * p],     qfh[c], fbl);
                mma_bf16(s[2 * p],     qfl[c], fbh);
                mma_bf16(s[2 * p + 1], qfh[c], fbh + 2);
                mma_bf16(s[2 * p + 1], qfh[c], fbl + 2);
                mma_bf16(s[2 * p + 1], qfl[c], fbh + 2);
            }
        }

        // ---- online softmax (Z bias-free), fold bias into P ----
        const int j0 = jt << 7;
        float tm0 = -1e30f, tm1 = -1e30f;
        #pragma unroll
        for (int nt = 0; nt < 16; nt++) {
            tm0 = fmaxf(tm0, fmaxf(s[nt][0], s[nt][1]));
            tm1 = fmaxf(tm1, fmaxf(s[nt][2], s[nt][3]));
        }
        tm0 = fmaxf(tm0, __shfl_xor_sync(0xffffffffu, tm0, 1));
        tm0 = fmaxf(tm0, __shfl_xor_sync(0xffffffffu, tm0, 2));
        tm1 = fmaxf(tm1, __shfl_xor_sync(0xffffffffu, tm1, 1));
        tm1 = fmaxf(tm1, __shfl_xor_sync(0xffffffffu, tm1, 2));
        const float mn0 = fmaxf(m0, tm0), mn1 = fmaxf(m1, tm1);
        const float sc0 = __expf(m0 - mn0), sc1 = __expf(m1 - mn1);
        m0 = mn0; m1 = mn1;

        float ps0 = 0.f, ps1 = 0.f;
        #pragma unroll
        for (int nt = 0; nt < 16; nt++) {
            const int jc = j0 + nt * 8 + 2 * t4;
            float2 bb0 = *(const float2*)&brow0[jc];
            float2 bb1 = *(const float2*)&brow1[jc];
            float p0 = __expf(s[nt][0] - mn0), p1 = __expf(s[nt][1] - mn0);
            float p2 = __expf(s[nt][2] - mn1), p3 = __expf(s[nt][3] - mn1);
            ps0 += p0 + p1; ps1 += p2 + p3;
            s[nt][0] = p0 * bb0.x; s[nt][1] = p1 * bb0.y;
            s[nt][2] = p2 * bb1.x; s[nt][3] = p3 * bb1.y;
        }
        ps0 += __shfl_xor_sync(0xffffffffu, ps0, 1);
        ps0 += __shfl_xor_sync(0xffffffffu, ps0, 2);
        ps1 += __shfl_xor_sync(0xffffffffu, ps1, 1);
        ps1 += __shfl_xor_sync(0xffffffffu, ps1, 2);
        z0 = z0 * sc0 + ps0;
        z1 = z1 * sc1 + ps1;

        // rescale O
        #pragma unroll
        for (int dt = 0; dt < 8; dt++) {
            acc_o[dt][0] *= sc0; acc_o[dt][1] *= sc0;
            acc_o[dt][2] *= sc1; acc_o[dt][3] *= sc1;
        }

        // ---- O += P V  (P regs split; 4 ldsm pairs -> 8 d-tiles) ----
        #pragma unroll
        for (int cc = 0; cc < 8; cc++) {
            uint32_t Ah[4], Al[4];
            split2(s[2 * cc][0],     s[2 * cc][1],     Ah[0], Al[0]);
            split2(s[2 * cc][2],     s[2 * cc][3],     Ah[1], Al[1]);
            split2(s[2 * cc + 1][0], s[2 * cc + 1][1], Ah[2], Al[2]);
            split2(s[2 * cc + 1][2], s[2 * cc + 1][3], Ah[3], Al[3]);
            #pragma unroll
            for (int dp = 0; dp < 4; dp++) {
                const uint32_t w = (uint32_t)((dp * 16 + br8) * 68 + cc * 8 + bk4) * 4;
                uint32_t vh4[4], vl4[4];
                ldsm4(vh4, smb + oVH + w);
                ldsm4(vl4, smb + oVL + w);
                mma_bf16(acc_o[2 * dp],     Ah, vh4);
                mma_bf16(acc_o[2 * dp],     Al, vh4);
                mma_bf16(acc_o[2 * dp],     Ah, vl4);
                mma_bf16(acc_o[2 * dp + 1], Ah, vh4 + 2);
                mma_bf16(acc_o[2 * dp + 1], Al, vh4 + 2);
                mma_bf16(acc_o[2 * dp + 1], Ah, vl4 + 2);
            }
        }
    }

    // ---- epilogue: O/Z, split-bf16 store (full 64 cols) ----
    const float i0 = 1.0f / z0, i1 = 1.0f / z1;
    #pragma unroll
    for (int dt = 0; dt < 8; dt++) {
        const int col = h * DD + dt * 8 + 2 * t4;
        const size_t o0 = ((size_t)(b * SS + qrow)) * HID + col;
        const size_t o1 = o0 + (size_t)8 * HID;
        uint32_t hp, lp;
        split2(acc_o[dt][0] * i0, acc_o[dt][1] * i0, hp, lp);
        *(uint32_t*)&ahi[o0] = hp; *(uint32_t*)&alo[o0] = lp;
        split2(acc_o[dt][2] * i1, acc_o[dt][3] * i1, hp, lp);
        *(uint32_t*)&ahi[o1] = hp; *(uint32_t*)&alo[o1] = lp;
    }
}

// ---------------------------------------------------------------------------
__global__ __launch_bounds__(256) void split_x(
    const float* __restrict__ in, __nv_bfloat16* __restrict__ hi,
    __nv_bfloat16* __restrict__ lo)
{
    size_t i4 = (size_t)blockIdx.x * 256 + threadIdx.x;
    float4 v = ((const float4*)in)[i4];
    uint32_t h0, l0, h1, l1;
    split2(v.x, v.y, h0, l0);
    split2(v.z, v.w, h1, l1);
    ((uint32_t*)hi)[i4 * 2] = h0; ((uint32_t*)lo)[i4 * 2] = l0;
    ((uint32_t*)hi)[i4 * 2 + 1] = h1; ((uint32_t*)lo)[i4 * 2 + 1] = l1;
}

__global__ void trans_w(const float* __restrict__ W,
                        __nv_bfloat16* __restrict__ Thi, __nv_bfloat16* __restrict__ Tlo)
{
    __shared__ float ts[32][33];
    const int n0 = blockIdx.x * 32, k0 = blockIdx.y * 32;
    const int tx = threadIdx.x, ty = threadIdx.y;
    #pragma unroll
    for (int i = 0; i < 4; i++)
        ts[ty + 8 * i][tx] = W[(size_t)(k0 + ty + 8 * i) * HID + n0 + tx];
    __syncthreads();
    #pragma unroll
    for (int i = 0; i < 4; i++) {
        __nv_bfloat16 h, l; bsplit(ts[tx][ty + 8 * i], h, l);
        size_t o = (size_t)(n0 + ty + 8 * i) * HID + k0 + tx;
        Thi[o] = h; Tlo[o] = l;
    }
}

// ---------------------------------------------------------------------------
extern "C" void kernel_launch(void* const* d_in, const int* in_sizes, int n_in,
                              void* d_out, int out_size)
{
    const float* x     = (const float*)d_in[0];
    const float* sinu  = (const float*)d_in[1];
    const float* abias = (const float*)d_in[2];
    const float* Wq    = (const float*)d_in[3];
    const float* bq    = (const float*)d_in[4];
    const float* Wk    = (const float*)d_in[5];
    const float* bk    = (const float*)d_in[6];
    const float* Wv    = (const float*)d_in[7];
    const float* bv    = (const float*)d_in[8];
    const float* Wo    = (const float*)d_in[9];
    float* out = (float*)d_out;

    __nv_bfloat16 *xhi, *xlo, *qhi, *qlo, *khi, *klo, *vthi, *vtlo, *ahi, *alo, *wh, *wl;
    cudaGetSymbolAddress((void**)&xhi, g_xhi);   cudaGetSymbolAddress((void**)&xlo, g_xlo);
    cudaGetSymbolAddress((void**)&qhi, g_qhi);   cudaGetSymbolAddress((void**)&qlo, g_qlo);
    cudaGetSymbolAddress((void**)&khi, g_khi);   cudaGetSymbolAddress((void**)&klo, g_klo);
    cudaGetSymbolAddress((void**)&vthi, g_vthi); cudaGetSymbolAddress((void**)&vtlo, g_vtlo);
    cudaGetSymbolAddress((void**)&ahi, g_ahi);   cudaGetSymbolAddress((void**)&alo, g_alo);
    cudaGetSymbolAddress((void**)&wh, g_wh);     cudaGetSymbolAddress((void**)&wl, g_wl);

    cudaFuncSetAttribute(gemm_proj<0>, cudaFuncAttributeMaxDynamicSharedMemorySize, 81920);
    cudaFuncSetAttribute(gemm_proj<1>, cudaFuncAttributeMaxDynamicSharedMemorySize, 81920);
    cudaFuncSetAttribute(gemm_proj<2>, cudaFuncAttributeMaxDynamicSharedMemorySize, 81920);
    cudaFuncSetAttribute(gemm_proj<3>, cudaFuncAttributeMaxDynamicSharedMemorySize, 81920);
    cudaFuncSetAttribute(flash_attn,   cudaFuncAttributeMaxDynamicSharedMemorySize, SM_TOT_W * 4);

    dim3 blk(256);
    const int WSZ = HID * HID;

    split_x<<<(int)(NELEM / 4 / 256), blk>>>(x, xhi, xlo);
    trans_w<<<dim3(32, 32), dim3(32, 8)>>>(Wq, wh + 0 * WSZ, wl + 0 * WSZ);
    trans_w<<<dim3(32, 32), dim3(32, 8)>>>(Wk, wh + 1 * WSZ, wl + 1 * WSZ);
    trans_w<<<dim3(32, 32), dim3(32, 8)>>>(Wv, wh + 2 * WSZ, wl + 2 * WSZ);
    trans_w<<<dim3(32, 32), dim3(32, 8)>>>(Wo, wh + 3 * WSZ, wl + 3 * WSZ);

    dim3 gproj(HID / 128, MTOT / 128);
    gemm_proj<1><<<gproj, blk, 81920>>>(xhi, xlo, wh + 0 * WSZ, wl + 0 * WSZ, bq, sinu,
                                        nullptr, qhi, qlo);
    gemm_proj<2><<<gproj, blk, 81920>>>(xhi, xlo, wh + 1 * WSZ, wl + 1 * WSZ, bk, sinu,
                                        nullptr, khi, klo);
    gemm_proj<3><<<gproj, blk, 81920>>>(xhi, xlo, wh + 2 * WSZ, wl + 2 * WSZ, bv, nullptr,
                                        nullptr, vthi, vtlo);

    flash_attn<<<dim3(BB * HH, SS / 128), blk, SM_TOT_W * 4>>>(
        qhi, qlo, khi, klo, vthi, vtlo, abias, ahi, alo);

    gemm_proj<0><<<gproj, blk, 81920>>>(ahi, alo, wh + 3 * WSZ, wl + 3 * WSZ, nullptr, nullptr,
                                        out, nullptr, nullptr);
}